// round 3
// baseline (speedup 1.0000x reference)
#include <cuda_runtime.h>
#include <cstddef>

#define HID 2048
#define KVD 512
#define TOK 4096   // B*S
#define SEQ 2048

// Scratch (allocation-guard-safe device globals)
__device__ float g_Q[(size_t)TOK * HID];
__device__ float g_K[(size_t)TOK * KVD];
__device__ float g_V[(size_t)TOK * KVD];
__device__ float g_C[(size_t)TOK * HID];

// ---------------------------------------------------------------------------
// SGEMM + bias: C[M,N] = A[M,K] @ W[K,N] + bias[N]
// 128x128 block, BK=16, 256 threads, 8x8 microtile per thread.
// ---------------------------------------------------------------------------
__global__ __launch_bounds__(256) void sgemm_bias_kernel(
    const float* __restrict__ A, const float* __restrict__ W,
    const float* __restrict__ bias, float* __restrict__ C,
    int M, int N, int K)
{
    __shared__ float As[16][132];   // A tile transposed [k][m], padded
    __shared__ float Ws[16][128];   // W tile [k][n]

    const int bm  = blockIdx.y * 128;
    const int bn  = blockIdx.x * 128;
    const int tid = threadIdx.x;
    const int tx  = tid & 15;
    const int ty  = tid >> 4;

    float acc[8][8];
    #pragma unroll
    for (int i = 0; i < 8; i++)
        #pragma unroll
        for (int j = 0; j < 8; j++) acc[i][j] = 0.0f;

    for (int k0 = 0; k0 < K; k0 += 16) {
        #pragma unroll
        for (int i = 0; i < 2; i++) {
            int p = tid + (i << 8);
            // A tile: 128 rows x 16 k  (512 float4 slots)
            int row = p >> 2;
            int kq  = (p & 3) << 2;
            float4 va = *(const float4*)(A + (size_t)(bm + row) * K + k0 + kq);
            As[kq + 0][row] = va.x;
            As[kq + 1][row] = va.y;
            As[kq + 2][row] = va.z;
            As[kq + 3][row] = va.w;
            // W tile: 16 k x 128 n (512 float4 slots)
            int kr = p >> 5;
            int nc = (p & 31) << 2;
            *(float4*)&Ws[kr][nc] =
                *(const float4*)(W + (size_t)(k0 + kr) * N + bn + nc);
        }
        __syncthreads();

        #pragma unroll
        for (int kk = 0; kk < 16; kk++) {
            float4 a0 = *(const float4*)&As[kk][ty * 4];
            float4 a1 = *(const float4*)&As[kk][ty * 4 + 64];
            float4 b0 = *(const float4*)&Ws[kk][tx * 4];
            float4 b1 = *(const float4*)&Ws[kk][tx * 4 + 64];
            float av[8] = {a0.x, a0.y, a0.z, a0.w, a1.x, a1.y, a1.z, a1.w};
            float bv[8] = {b0.x, b0.y, b0.z, b0.w, b1.x, b1.y, b1.z, b1.w};
            #pragma unroll
            for (int i = 0; i < 8; i++)
                #pragma unroll
                for (int j = 0; j < 8; j++)
                    acc[i][j] = fmaf(av[i], bv[j], acc[i][j]);
        }
        __syncthreads();
    }

    #pragma unroll
    for (int i = 0; i < 8; i++) {
        int row = bm + ((i >> 2) << 6) + ty * 4 + (i & 3);
        #pragma unroll
        for (int jq = 0; jq < 2; jq++) {
            int col = bn + (jq << 6) + tx * 4;
            float4 v;
            v.x = acc[i][jq * 4 + 0] + bias[col + 0];
            v.y = acc[i][jq * 4 + 1] + bias[col + 1];
            v.z = acc[i][jq * 4 + 2] + bias[col + 2];
            v.w = acc[i][jq * 4 + 3] + bias[col + 3];
            *(float4*)(C + (size_t)row * N + col) = v;
        }
    }
}

// ---------------------------------------------------------------------------
// Flash attention, fp32. Block = (batch b, q-head h, 128-query tile).
// Loops 64-key tiles with online softmax. Head dim 64, GQA kv = h>>2.
// ---------------------------------------------------------------------------
#define QSTR 132   // padded row-stride for [d][qrow] / [key][qrow] layouts
#define KSTR 68    // padded row-stride for [d][key]
#define ATTN_SMEM ((64*QSTR + 64*KSTR + 64*64 + 64*QSTR) * 4)

__global__ __launch_bounds__(256) void attn_kernel()
{
    extern __shared__ float sm[];
    float* Qt = sm;                  // [64][QSTR]  q transposed, pre-scaled
    float* Kt = Qt + 64 * QSTR;      // [64][KSTR]  k transposed
    float* Vs = Kt + 64 * KSTR;      // [64][64]    v row-major [key][d]
    float* Pt = Vs + 64 * 64;        // [64][QSTR]  probs transposed [key][qrow]

    const int qt  = blockIdx.x;      // 0..15
    const int h   = blockIdx.y;      // 0..31
    const int b   = blockIdx.z;      // 0..1
    const int kvh = h >> 2;
    const int tid = threadIdx.x;
    const int tx  = tid & 15;
    const int ty  = tid >> 4;
    const int t0  = b * SEQ + qt * 128;

    // Load Q tile [128 q x 64 d], scaled by 1/sqrt(64), stored transposed.
    #pragma unroll
    for (int i = 0; i < 8; i++) {
        int p   = tid + (i << 8);
        int row = p >> 4;
        int dq  = (p & 15) << 2;
        float4 v = *(const float4*)(g_Q + (size_t)(t0 + row) * HID + h * 64 + dq);
        Qt[(dq + 0) * QSTR + row] = v.x * 0.125f;
        Qt[(dq + 1) * QSTR + row] = v.y * 0.125f;
        Qt[(dq + 2) * QSTR + row] = v.z * 0.125f;
        Qt[(dq + 3) * QSTR + row] = v.w * 0.125f;
    }

    // Per-thread rows: {ty*4+i} and {64+ty*4+i}; cols: tx*4+j
    float m[8], l[8], o[8][4];
    #pragma unroll
    for (int i = 0; i < 8; i++) {
        m[i] = -1e30f; l[i] = 0.0f;
        #pragma unroll
        for (int j = 0; j < 4; j++) o[i][j] = 0.0f;
    }

    for (int kt0 = 0; kt0 < SEQ; kt0 += 64) {
        __syncthreads();   // prev iteration's reads of Kt/Vs/Pt complete
        #pragma unroll
        for (int i = 0; i < 4; i++) {
            int p   = tid + (i << 8);
            int key = p >> 4;
            int dq  = (p & 15) << 2;
            size_t gidx = (size_t)(b * SEQ + kt0 + key) * KVD + kvh * 64 + dq;
            float4 kv4 = *(const float4*)(g_K + gidx);
            Kt[(dq + 0) * KSTR + key] = kv4.x;
            Kt[(dq + 1) * KSTR + key] = kv4.y;
            Kt[(dq + 2) * KSTR + key] = kv4.z;
            Kt[(dq + 3) * KSTR + key] = kv4.w;
            *(float4*)(Vs + key * 64 + dq) = *(const float4*)(g_V + gidx);
        }
        __syncthreads();

        // S = Q @ K^T  (128 x 64, reduce over d=64)
        float s[8][4];
        #pragma unroll
        for (int i = 0; i < 8; i++)
            #pragma unroll
            for (int j = 0; j < 4; j++) s[i][j] = 0.0f;

        #pragma unroll 16
        for (int kk = 0; kk < 64; kk++) {
            float4 a0 = *(const float4*)(Qt + kk * QSTR + ty * 4);
            float4 a1 = *(const float4*)(Qt + kk * QSTR + 64 + ty * 4);
            float4 b4 = *(const float4*)(Kt + kk * KSTR + tx * 4);
            float av[8] = {a0.x, a0.y, a0.z, a0.w, a1.x, a1.y, a1.z, a1.w};
            float bv[4] = {b4.x, b4.y, b4.z, b4.w};
            #pragma unroll
            for (int i = 0; i < 8; i++)
                #pragma unroll
                for (int j = 0; j < 4; j++)
                    s[i][j] = fmaf(av[i], bv[j], s[i][j]);
        }

        // Online softmax (row groups = 16 lanes sharing ty; shfl over tx)
        #pragma unroll
        for (int i = 0; i < 8; i++) {
            float tm = fmaxf(fmaxf(s[i][0], s[i][1]), fmaxf(s[i][2], s[i][3]));
            #pragma unroll
            for (int off = 8; off; off >>= 1)
                tm = fmaxf(tm, __shfl_xor_sync(0xffffffffu, tm, off));
            float mn = fmaxf(m[i], tm);
            float f  = __expf(m[i] - mn);
            m[i] = mn;
            float ps = 0.0f;
            #pragma unroll
            for (int j = 0; j < 4; j++) {
                s[i][j] = __expf(s[i][j] - mn);
                ps += s[i][j];
            }
            #pragma unroll
            for (int off = 8; off; off >>= 1)
                ps += __shfl_xor_sync(0xffffffffu, ps, off);
            l[i] = l[i] * f + ps;
            #pragma unroll
            for (int j = 0; j < 4; j++) o[i][j] *= f;
            int row = ((i >> 2) << 6) + ty * 4 + (i & 3);
            #pragma unroll
            for (int j = 0; j < 4; j++)
                Pt[(tx * 4 + j) * QSTR + row] = s[i][j];
        }
        __syncthreads();   // Pt complete

        // O += P @ V  (128 x 64, reduce over 64 keys)
        #pragma unroll 16
        for (int kk = 0; kk < 64; kk++) {
            float4 a0 = *(const float4*)(Pt + kk * QSTR + ty * 4);
            float4 a1 = *(const float4*)(Pt + kk * QSTR + 64 + ty * 4);
            float4 b4 = *(const float4*)(Vs + kk * 64 + tx * 4);
            float av[8] = {a0.x, a0.y, a0.z, a0.w, a1.x, a1.y, a1.z, a1.w};
            float bv[4] = {b4.x, b4.y, b4.z, b4.w};
            #pragma unroll
            for (int i = 0; i < 8; i++)
                #pragma unroll
                for (int j = 0; j < 4; j++)
                    o[i][j] = fmaf(av[i], bv[j], o[i][j]);
        }
    }

    // Normalize and write context
    #pragma unroll
    for (int i = 0; i < 8; i++) {
        float inv = 1.0f / l[i];
        int row = t0 + ((i >> 2) << 6) + ty * 4 + (i & 3);
        float4 v;
        v.x = o[i][0] * inv;
        v.y = o[i][1] * inv;
        v.z = o[i][2] * inv;
        v.w = o[i][3] * inv;
        *(float4*)(g_C + (size_t)row * HID + h * 64 + tx * 4) = v;
    }
}

// ---------------------------------------------------------------------------
extern "C" void kernel_launch(void* const* d_in, const int* in_sizes, int n_in,
                              void* d_out, int out_size)
{
    const float* x  = (const float*)d_in[0];
    const float* Wq = (const float*)d_in[1];
    const float* bq = (const float*)d_in[2];
    const float* Wk = (const float*)d_in[3];
    const float* bk = (const float*)d_in[4];
    const float* Wv = (const float*)d_in[5];
    const float* bv = (const float*)d_in[6];
    const float* Wo = (const float*)d_in[7];
    const float* bo = (const float*)d_in[8];
    float* out = (float*)d_out;

    float *q, *k, *v, *c;
    cudaGetSymbolAddress((void**)&q, g_Q);
    cudaGetSymbolAddress((void**)&k, g_K);
    cudaGetSymbolAddress((void**)&v, g_V);
    cudaGetSymbolAddress((void**)&c, g_C);

    cudaFuncSetAttribute(attn_kernel,
                         cudaFuncAttributeMaxDynamicSharedMemorySize,
                         ATTN_SMEM);

    dim3 blk(256);
    // Projections
    sgemm_bias_kernel<<<dim3(16, 32), blk>>>(x, Wq, bq, q, TOK, HID, HID);
    sgemm_bias_kernel<<<dim3(4, 32),  blk>>>(x, Wk, bk, k, TOK, KVD, HID);
    sgemm_bias_kernel<<<dim3(4, 32),  blk>>>(x, Wv, bv, v, TOK, KVD, HID);
    // Attention: grid = (q tiles, heads, batch)
    attn_kernel<<<dim3(16, 32, 2), blk, ATTN_SMEM>>>();
    // Output projection
    sgemm_bias_kernel<<<dim3(16, 32), blk>>>(c, Wo, bo, out, TOK, HID, HID);
}

// round 11
// speedup vs baseline: 1.4726x; 1.4726x over previous
#include <cuda_runtime.h>
#include <cuda_bf16.h>
#include <cstdint>
#include <cstddef>

#define HID 2048
#define KVD 512
#define TOK 4096   // B*S
#define SEQ 2048

// ---------------------------------------------------------------------------
// Scratch (allocation-guard-safe device globals)
// ---------------------------------------------------------------------------
__device__ float g_Q[(size_t)TOK * HID];
__device__ float g_K[(size_t)TOK * KVD];
__device__ float g_V[(size_t)TOK * KVD];
__device__ float g_C[(size_t)TOK * HID];

__device__ __nv_bfloat16 g_Xhi[(size_t)TOK * HID];
__device__ __nv_bfloat16 g_Xlo[(size_t)TOK * HID];
__device__ __nv_bfloat16 g_Chi[(size_t)TOK * HID];
__device__ __nv_bfloat16 g_Clo[(size_t)TOK * HID];
__device__ __nv_bfloat16 g_WqThi[(size_t)HID * HID];
__device__ __nv_bfloat16 g_WqTlo[(size_t)HID * HID];
__device__ __nv_bfloat16 g_WkThi[(size_t)KVD * HID];
__device__ __nv_bfloat16 g_WkTlo[(size_t)KVD * HID];
__device__ __nv_bfloat16 g_WvThi[(size_t)KVD * HID];
__device__ __nv_bfloat16 g_WvTlo[(size_t)KVD * HID];
__device__ __nv_bfloat16 g_WoThi[(size_t)HID * HID];
__device__ __nv_bfloat16 g_WoTlo[(size_t)HID * HID];

// ---------------------------------------------------------------------------
// Baseline-ISA helpers (NO 'a'-suffix features: harness targets sm_103 plain)
// ---------------------------------------------------------------------------
__device__ __forceinline__ uint32_t smem_u32(const void* p) {
    uint32_t a;
    asm("{ .reg .u64 t; cvta.to.shared.u64 t, %1; cvt.u32.u64 %0, t; }"
        : "=r"(a) : "l"(p));
    return a;
}

__device__ __forceinline__ void cp16(uint32_t s, const void* g) {
    asm volatile("cp.async.cg.shared.global [%0], [%1], 16;" :: "r"(s), "l"(g));
}
#define CP_COMMIT() asm volatile("cp.async.commit_group;" ::: "memory")
#define CP_WAIT1()  asm volatile("cp.async.wait_group 1;" ::: "memory")
#define CP_WAIT0()  asm volatile("cp.async.wait_group 0;" ::: "memory")

__device__ __forceinline__ void ldsm4(uint32_t& r0, uint32_t& r1,
                                      uint32_t& r2, uint32_t& r3, uint32_t a) {
    asm volatile("ldmatrix.sync.aligned.m8n8.x4.shared.b16 {%0,%1,%2,%3}, [%4];"
                 : "=r"(r0), "=r"(r1), "=r"(r2), "=r"(r3) : "r"(a));
}

__device__ __forceinline__ void mma_bf16(float* d, const uint32_t* a,
                                         const uint32_t* b) {
    asm volatile(
        "mma.sync.aligned.m16n8k16.row.col.f32.bf16.bf16.f32 "
        "{%0,%1,%2,%3}, {%4,%5,%6,%7}, {%8,%9}, {%0,%1,%2,%3};"
        : "+f"(d[0]), "+f"(d[1]), "+f"(d[2]), "+f"(d[3])
        : "r"(a[0]), "r"(a[1]), "r"(a[2]), "r"(a[3]), "r"(b[0]), "r"(b[1]));
}

// ---------------------------------------------------------------------------
// fp32 -> (hi, lo) bf16 split, same layout. n4 = element count / 4.
// ---------------------------------------------------------------------------
__global__ __launch_bounds__(256) void split_kernel(
    const float* __restrict__ in, __nv_bfloat16* __restrict__ hi,
    __nv_bfloat16* __restrict__ lo, int n4)
{
    int i = blockIdx.x * blockDim.x + threadIdx.x;
    if (i >= n4) return;
    float4 v = ((const float4*)in)[i];
    __nv_bfloat16 h0 = __float2bfloat16(v.x);
    __nv_bfloat16 h1 = __float2bfloat16(v.y);
    __nv_bfloat16 h2 = __float2bfloat16(v.z);
    __nv_bfloat16 h3 = __float2bfloat16(v.w);
    __nv_bfloat16 l0 = __float2bfloat16(v.x - __bfloat162float(h0));
    __nv_bfloat16 l1 = __float2bfloat16(v.y - __bfloat162float(h1));
    __nv_bfloat16 l2 = __float2bfloat16(v.z - __bfloat162float(h2));
    __nv_bfloat16 l3 = __float2bfloat16(v.w - __bfloat162float(h3));
    __nv_bfloat162* H = (__nv_bfloat162*)hi;
    __nv_bfloat162* L = (__nv_bfloat162*)lo;
    H[2 * i]     = __nv_bfloat162{h0, h1};
    H[2 * i + 1] = __nv_bfloat162{h2, h3};
    L[2 * i]     = __nv_bfloat162{l0, l1};
    L[2 * i + 1] = __nv_bfloat162{l2, l3};
}

// ---------------------------------------------------------------------------
// W [K,N] fp32 -> WT [N,K] hi/lo bf16 (tiled transpose + split)
// ---------------------------------------------------------------------------
__global__ __launch_bounds__(256) void wsplit_kernel(
    const float* __restrict__ W, __nv_bfloat16* __restrict__ Thi,
    __nv_bfloat16* __restrict__ Tlo, int K, int N)
{
    __shared__ float t[32][33];
    int n0 = blockIdx.x * 32, k0 = blockIdx.y * 32;
    int tx = threadIdx.x, ty = threadIdx.y;
    #pragma unroll
    for (int r = 0; r < 4; r++)
        t[ty + 8 * r][tx] = W[(size_t)(k0 + ty + 8 * r) * N + n0 + tx];
    __syncthreads();
    #pragma unroll
    for (int r = 0; r < 4; r++) {
        float v = t[tx][ty + 8 * r];
        __nv_bfloat16 h = __float2bfloat16(v);
        __nv_bfloat16 l = __float2bfloat16(v - __bfloat162float(h));
        size_t idx = (size_t)(n0 + ty + 8 * r) * K + k0 + tx;
        Thi[idx] = h;
        Tlo[idx] = l;
    }
}

// ---------------------------------------------------------------------------
// Split-bf16 HMMA GEMM: C[M,N] = A @ W + bias
// A = Ahi/Alo [M,2048] K-major; B = Bhi/Blo [N,2048] K-major.
// CTA tile 128x128, BK=64, 8 warps (2m x 4n), warp tile 64x32.
// 3 mma terms per k16: hi*hi + hi*lo + lo*hi  (error ~2^-16).
// smem rows are exactly 128B, so SW128 swizzle == kbyte ^ ((row&7)<<4).
// ---------------------------------------------------------------------------
#define BM 128
#define BN 128
#define BK 64
#define GK 2048
#define NCH (GK / BK)          // 32
#define OFF_AHI 0
#define OFF_ALO 16384
#define OFF_BHI 32768
#define OFF_BLO 49152
#define STG 65536
#define GEMM_SMEM (2 * STG)

__global__ __launch_bounds__(256) void gemm_hmma_kernel(
    const __nv_bfloat16* __restrict__ Ahi, const __nv_bfloat16* __restrict__ Alo,
    const __nv_bfloat16* __restrict__ Bhi, const __nv_bfloat16* __restrict__ Blo,
    const float* __restrict__ bias, float* __restrict__ C, int N)
{
    extern __shared__ char dsm[];
    const uint32_t sb = smem_u32(dsm);

    const int tid  = threadIdx.x;
    const int lane = tid & 31;
    const int w    = tid >> 5;
    const int wm   = w & 1;        // 0..1 -> 64-row slab
    const int wn   = w >> 1;       // 0..3 -> 32-col slab
    const int bm   = blockIdx.y * BM;
    const int bn   = blockIdx.x * BN;

    float acc[4][4][4];
    #pragma unroll
    for (int mt = 0; mt < 4; mt++)
        #pragma unroll
        for (int nt = 0; nt < 4; nt++)
            #pragma unroll
            for (int r = 0; r < 4; r++) acc[mt][nt][r] = 0.0f;

    auto load_chunk = [&](int c, int s) {
        uint32_t st = sb + (uint32_t)s * STG;
        int k0 = c * BK;
        #pragma unroll
        for (int i = 0; i < 4; i++) {
            int u = tid + (i << 8);
            int row = u >> 3, c8 = u & 7;
            uint32_t off = (uint32_t)row * 128 +
                           (((uint32_t)c8 * 16) ^ (((uint32_t)(row & 7)) << 4));
            size_t ga = (size_t)(bm + row) * GK + k0 + c8 * 8;
            size_t gb = (size_t)(bn + row) * GK + k0 + c8 * 8;
            cp16(st + OFF_AHI + off, Ahi + ga);
            cp16(st + OFF_ALO + off, Alo + ga);
            cp16(st + OFF_BHI + off, Bhi + gb);
            cp16(st + OFF_BLO + off, Blo + gb);
        }
        CP_COMMIT();
    };

    load_chunk(0, 0);
    load_chunk(1, 1);

    // Per-lane ldmatrix address components (swizzle reduces to XOR-on-kbyte)
    const uint32_t l15  = lane & 15;
    const uint32_t kx   = ((uint32_t)(lane & 7)) << 4;
    const uint32_t hi16 = ((uint32_t)(lane >> 4)) << 4;
    const uint32_t aRow = (uint32_t)(wm * 64 + l15) * 128;
    const uint32_t bRow = (uint32_t)(wn * 32 + l15) * 128;

    for (int c = 0; c < NCH; c++) {
        if (c >= NCH - 1) CP_WAIT0(); else CP_WAIT1();
        __syncthreads();
        uint32_t st = sb + (uint32_t)(c & 1) * STG;

        #pragma unroll
        for (int ks = 0; ks < 4; ks++) {
            uint32_t kp = ((uint32_t)(ks * 32) + hi16) ^ kx;

            uint32_t ah[16], bh[8], bl[8], al[16];
            #pragma unroll
            for (int mt = 0; mt < 4; mt++)
                ldsm4(ah[mt * 4], ah[mt * 4 + 1], ah[mt * 4 + 2], ah[mt * 4 + 3],
                      st + OFF_AHI + aRow + mt * 2048 + kp);
            #pragma unroll
            for (int g = 0; g < 2; g++) {
                uint32_t r0, r1, r2, r3;
                ldsm4(r0, r1, r2, r3, st + OFF_BHI + bRow + g * 2048 + kp);
                bh[g * 4 + 0] = r0; bh[g * 4 + 1] = r2;   // nt = 2g   : {r0,r2}
                bh[g * 4 + 2] = r1; bh[g * 4 + 3] = r3;   // nt = 2g+1 : {r1,r3}
            }
            #pragma unroll
            for (int mt = 0; mt < 4; mt++)
                #pragma unroll
                for (int nt = 0; nt < 4; nt++)
                    mma_bf16(acc[mt][nt], &ah[mt * 4], &bh[nt * 2]);

            #pragma unroll
            for (int g = 0; g < 2; g++) {
                uint32_t r0, r1, r2, r3;
                ldsm4(r0, r1, r2, r3, st + OFF_BLO + bRow + g * 2048 + kp);
                bl[g * 4 + 0] = r0; bl[g * 4 + 1] = r2;
                bl[g * 4 + 2] = r1; bl[g * 4 + 3] = r3;
            }
            #pragma unroll
            for (int mt = 0; mt < 4; mt++)
                #pragma unroll
                for (int nt = 0; nt < 4; nt++)
                    mma_bf16(acc[mt][nt], &ah[mt * 4], &bl[nt * 2]);

            #pragma unroll
            for (int mt = 0; mt < 4; mt++)
                ldsm4(al[mt * 4], al[mt * 4 + 1], al[mt * 4 + 2], al[mt * 4 + 3],
                      st + OFF_ALO + aRow + mt * 2048 + kp);
            #pragma unroll
            for (int mt = 0; mt < 4; mt++)
                #pragma unroll
                for (int nt = 0; nt < 4; nt++)
                    mma_bf16(acc[mt][nt], &al[mt * 4], &bh[nt * 2]);
        }

        __syncthreads();
        if (c + 2 < NCH) load_chunk(c + 2, c & 1);
    }

    // Epilogue: bias + fp32 store (thread owns cols (lane&3)*2, +1 per n-tile)
    float bs[4][2];
    #pragma unroll
    for (int nt = 0; nt < 4; nt++) {
        int col = bn + wn * 32 + nt * 8 + (lane & 3) * 2;
        bs[nt][0] = bias[col];
        bs[nt][1] = bias[col + 1];
    }
    #pragma unroll
    for (int mt = 0; mt < 4; mt++) {
        #pragma unroll
        for (int rg = 0; rg < 2; rg++) {
            int row = bm + wm * 64 + mt * 16 + rg * 8 + (lane >> 2);
            #pragma unroll
            for (int nt = 0; nt < 4; nt++) {
                int col = bn + wn * 32 + nt * 8 + (lane & 3) * 2;
                float2 v;
                v.x = acc[mt][nt][rg * 2 + 0] + bs[nt][0];
                v.y = acc[mt][nt][rg * 2 + 1] + bs[nt][1];
                *(float2*)(C + (size_t)row * N + col) = v;
            }
        }
    }
}

// ---------------------------------------------------------------------------
// Flash attention, fp32 (verified in R3; 2 CTAs/SM)
// ---------------------------------------------------------------------------
#define QSTR 132
#define KSTR 68
#define ATTN_SMEM ((64 * QSTR + 64 * KSTR + 64 * 64 + 64 * QSTR) * 4)

__global__ __launch_bounds__(256, 2) void attn_kernel()
{
    extern __shared__ float sm[];
    float* Qt = sm;
    float* Kt = Qt + 64 * QSTR;
    float* Vs = Kt + 64 * KSTR;
    float* Pt = Vs + 64 * 64;

    const int qt  = blockIdx.x;
    const int h   = blockIdx.y;
    const int b   = blockIdx.z;
    const int kvh = h >> 2;
    const int tid = threadIdx.x;
    const int tx  = tid & 15;
    const int ty  = tid >> 4;
    const int t0  = b * SEQ + qt * 128;

    #pragma unroll
    for (int i = 0; i < 8; i++) {
        int p   = tid + (i << 8);
        int row = p >> 4;
        int dq  = (p & 15) << 2;
        float4 v = *(const float4*)(g_Q + (size_t)(t0 + row) * HID + h * 64 + dq);
        Qt[(dq + 0) * QSTR + row] = v.x * 0.125f;
        Qt[(dq + 1) * QSTR + row] = v.y * 0.125f;
        Qt[(dq + 2) * QSTR + row] = v.z * 0.125f;
        Qt[(dq + 3) * QSTR + row] = v.w * 0.125f;
    }

    float m[8], l[8], o[8][4];
    #pragma unroll
    for (int i = 0; i < 8; i++) {
        m[i] = -1e30f; l[i] = 0.0f;
        #pragma unroll
        for (int j = 0; j < 4; j++) o[i][j] = 0.0f;
    }

    for (int kt0 = 0; kt0 < SEQ; kt0 += 64) {
        __syncthreads();
        #pragma unroll
        for (int i = 0; i < 4; i++) {
            int p   = tid + (i << 8);
            int key = p >> 4;
            int dq  = (p & 15) << 2;
            size_t gidx = (size_t)(b * SEQ + kt0 + key) * KVD + kvh * 64 + dq;
            float4 kv4 = *(const float4*)(g_K + gidx);
            Kt[(dq + 0) * KSTR + key] = kv4.x;
            Kt[(dq + 1) * KSTR + key] = kv4.y;
            Kt[(dq + 2) * KSTR + key] = kv4.z;
            Kt[(dq + 3) * KSTR + key] = kv4.w;
            *(float4*)(Vs + key * 64 + dq) = *(const float4*)(g_V + gidx);
        }
        __syncthreads();

        float s[8][4];
        #pragma unroll
        for (int i = 0; i < 8; i++)
            #pragma unroll
            for (int j = 0; j < 4; j++) s[i][j] = 0.0f;

        #pragma unroll 16
        for (int kk = 0; kk < 64; kk++) {
            float4 a0 = *(const float4*)(Qt + kk * QSTR + ty * 4);
            float4 a1 = *(const float4*)(Qt + kk * QSTR + 64 + ty * 4);
            float4 b4 = *(const float4*)(Kt + kk * KSTR + tx * 4);
            float av[8] = {a0.x, a0.y, a0.z, a0.w, a1.x, a1.y, a1.z, a1.w};
            float bv[4] = {b4.x, b4.y, b4.z, b4.w};
            #pragma unroll
            for (int i = 0; i < 8; i++)
                #pragma unroll
                for (int j = 0; j < 4; j++)
                    s[i][j] = fmaf(av[i], bv[j], s[i][j]);
        }

        #pragma unroll
        for (int i = 0; i < 8; i++) {
            float tm = fmaxf(fmaxf(s[i][0], s[i][1]), fmaxf(s[i][2], s[i][3]));
            #pragma unroll
            for (int off = 8; off; off >>= 1)
                tm = fmaxf(tm, __shfl_xor_sync(0xffffffffu, tm, off));
            float mn = fmaxf(m[i], tm);
            float f  = __expf(m[i] - mn);
            m[i] = mn;
            float ps = 0.0f;
            #pragma unroll
            for (int j = 0; j < 4; j++) {
                s[i][j] = __expf(s[i][j] - mn);
                ps += s[i][j];
            }
            #pragma unroll
            for (int off = 8; off; off >>= 1)
                ps += __shfl_xor_sync(0xffffffffu, ps, off);
            l[i] = l[i] * f + ps;
            #pragma unroll
            for (int j = 0; j < 4; j++) o[i][j] *= f;
            int row = ((i >> 2) << 6) + ty * 4 + (i & 3);
            #pragma unroll
            for (int j = 0; j < 4; j++)
                Pt[(tx * 4 + j) * QSTR + row] = s[i][j];
        }
        __syncthreads();

        #pragma unroll 16
        for (int kk = 0; kk < 64; kk++) {
            float4 a0 = *(const float4*)(Pt + kk * QSTR + ty * 4);
            float4 a1 = *(const float4*)(Pt + kk * QSTR + 64 + ty * 4);
            float4 b4 = *(const float4*)(Vs + kk * 64 + tx * 4);
            float av[8] = {a0.x, a0.y, a0.z, a0.w, a1.x, a1.y, a1.z, a1.w};
            float bv[4] = {b4.x, b4.y, b4.z, b4.w};
            #pragma unroll
            for (int i = 0; i < 8; i++)
                #pragma unroll
                for (int j = 0; j < 4; j++)
                    o[i][j] = fmaf(av[i], bv[j], o[i][j]);
        }
    }

    #pragma unroll
    for (int i = 0; i < 8; i++) {
        float inv = 1.0f / l[i];
        int row = t0 + ((i >> 2) << 6) + ty * 4 + (i & 3);
        float4 v;
        v.x = o[i][0] * inv;
        v.y = o[i][1] * inv;
        v.z = o[i][2] * inv;
        v.w = o[i][3] * inv;
        *(float4*)(g_C + (size_t)row * HID + h * 64 + tx * 4) = v;
    }
}

// ---------------------------------------------------------------------------
extern "C" void kernel_launch(void* const* d_in, const int* in_sizes, int n_in,
                              void* d_out, int out_size)
{
    const float* x  = (const float*)d_in[0];
    const float* Wq = (const float*)d_in[1];
    const float* bq = (const float*)d_in[2];
    const float* Wk = (const float*)d_in[3];
    const float* bk = (const float*)d_in[4];
    const float* Wv = (const float*)d_in[5];
    const float* bv = (const float*)d_in[6];
    const float* Wo = (const float*)d_in[7];
    const float* bo = (const float*)d_in[8];
    float* out = (float*)d_out;

    float *q, *k, *v, *c;
    __nv_bfloat16 *xhi, *xlo, *chi, *clo;
    __nv_bfloat16 *wqh, *wql, *wkh, *wkl, *wvh, *wvl, *woh, *wol;
    cudaGetSymbolAddress((void**)&q, g_Q);
    cudaGetSymbolAddress((void**)&k, g_K);
    cudaGetSymbolAddress((void**)&v, g_V);
    cudaGetSymbolAddress((void**)&c, g_C);
    cudaGetSymbolAddress((void**)&xhi, g_Xhi);
    cudaGetSymbolAddress((void**)&xlo, g_Xlo);
    cudaGetSymbolAddress((void**)&chi, g_Chi);
    cudaGetSymbolAddress((void**)&clo, g_Clo);
    cudaGetSymbolAddress((void**)&wqh, g_WqThi);
    cudaGetSymbolAddress((void**)&wql, g_WqTlo);
    cudaGetSymbolAddress((void**)&wkh, g_WkThi);
    cudaGetSymbolAddress((void**)&wkl, g_WkTlo);
    cudaGetSymbolAddress((void**)&wvh, g_WvThi);
    cudaGetSymbolAddress((void**)&wvl, g_WvTlo);
    cudaGetSymbolAddress((void**)&woh, g_WoThi);
    cudaGetSymbolAddress((void**)&wol, g_WoTlo);

    cudaFuncSetAttribute(attn_kernel,
                         cudaFuncAttributeMaxDynamicSharedMemorySize, ATTN_SMEM);
    cudaFuncSetAttribute(gemm_hmma_kernel,
                         cudaFuncAttributeMaxDynamicSharedMemorySize, GEMM_SMEM);

    dim3 blk(256);
    dim3 tblk(32, 8);

    // Operand conversion
    int n4x = TOK * HID / 4;
    split_kernel<<<(n4x + 255) / 256, blk>>>(x, xhi, xlo, n4x);
    wsplit_kernel<<<dim3(HID / 32, HID / 32), tblk>>>(Wq, wqh, wql, HID, HID);
    wsplit_kernel<<<dim3(KVD / 32, HID / 32), tblk>>>(Wk, wkh, wkl, HID, KVD);
    wsplit_kernel<<<dim3(KVD / 32, HID / 32), tblk>>>(Wv, wvh, wvl, HID, KVD);
    wsplit_kernel<<<dim3(HID / 32, HID / 32), tblk>>>(Wo, woh, wol, HID, HID);

    // Projections (HMMA mma.sync, split bf16 x3)
    gemm_hmma_kernel<<<dim3(HID / BN, TOK / BM), blk, GEMM_SMEM>>>(
        xhi, xlo, wqh, wql, bq, q, HID);
    gemm_hmma_kernel<<<dim3(KVD / BN, TOK / BM), blk, GEMM_SMEM>>>(
        xhi, xlo, wkh, wkl, bk, k, KVD);
    gemm_hmma_kernel<<<dim3(KVD / BN, TOK / BM), blk, GEMM_SMEM>>>(
        xhi, xlo, wvh, wvl, bv, v, KVD);

    // Attention
    attn_kernel<<<dim3(16, 32, 2), blk, ATTN_SMEM>>>();

    // Output projection
    split_kernel<<<(n4x + 255) / 256, blk>>>(c, chi, clo, n4x);
    gemm_hmma_kernel<<<dim3(HID / BN, TOK / BM), blk, GEMM_SMEM>>>(
        chi, clo, woh, wol, bo, out, HID);
}

// round 13
// speedup vs baseline: 2.6554x; 1.8032x over previous
#include <cuda_runtime.h>
#include <cuda_bf16.h>
#include <cstdint>
#include <cstddef>

#define HID 2048
#define KVD 512
#define TOK 4096   // B*S
#define SEQ 2048

// ---------------------------------------------------------------------------
// Scratch (allocation-guard-safe device globals)
// ---------------------------------------------------------------------------
__device__ __nv_bfloat16 g_Xhi[(size_t)TOK * HID];
__device__ __nv_bfloat16 g_Xlo[(size_t)TOK * HID];
__device__ __nv_bfloat16 g_Qhi[(size_t)TOK * HID];
__device__ __nv_bfloat16 g_Qlo[(size_t)TOK * HID];
__device__ __nv_bfloat16 g_Khi[(size_t)TOK * KVD];
__device__ __nv_bfloat16 g_Klo[(size_t)TOK * KVD];
__device__ __nv_bfloat16 g_Vhi[(size_t)TOK * KVD];
__device__ __nv_bfloat16 g_Vlo[(size_t)TOK * KVD];
__device__ __nv_bfloat16 g_Chi[(size_t)TOK * HID];
__device__ __nv_bfloat16 g_Clo[(size_t)TOK * HID];
__device__ __nv_bfloat16 g_WqThi[(size_t)HID * HID];
__device__ __nv_bfloat16 g_WqTlo[(size_t)HID * HID];
__device__ __nv_bfloat16 g_WkThi[(size_t)KVD * HID];
__device__ __nv_bfloat16 g_WkTlo[(size_t)KVD * HID];
__device__ __nv_bfloat16 g_WvThi[(size_t)KVD * HID];
__device__ __nv_bfloat16 g_WvTlo[(size_t)KVD * HID];
__device__ __nv_bfloat16 g_WoThi[(size_t)HID * HID];
__device__ __nv_bfloat16 g_WoTlo[(size_t)HID * HID];

// ---------------------------------------------------------------------------
// Baseline-ISA helpers (harness targets sm_103 plain: no tcgen05/TMA)
// ---------------------------------------------------------------------------
__device__ __forceinline__ uint32_t smem_u32(const void* p) {
    uint32_t a;
    asm("{ .reg .u64 t; cvta.to.shared.u64 t, %1; cvt.u32.u64 %0, t; }"
        : "=r"(a) : "l"(p));
    return a;
}

__device__ __forceinline__ void cp16(uint32_t s, const void* g) {
    asm volatile("cp.async.cg.shared.global [%0], [%1], 16;" :: "r"(s), "l"(g));
}
#define CP_COMMIT() asm volatile("cp.async.commit_group;" ::: "memory")
#define CP_WAIT1()  asm volatile("cp.async.wait_group 1;" ::: "memory")
#define CP_WAIT0()  asm volatile("cp.async.wait_group 0;" ::: "memory")

__device__ __forceinline__ void ldsm4(uint32_t& r0, uint32_t& r1,
                                      uint32_t& r2, uint32_t& r3, uint32_t a) {
    asm volatile("ldmatrix.sync.aligned.m8n8.x4.shared.b16 {%0,%1,%2,%3}, [%4];"
                 : "=r"(r0), "=r"(r1), "=r"(r2), "=r"(r3) : "r"(a));
}
__device__ __forceinline__ void ldsm4t(uint32_t& r0, uint32_t& r1,
                                       uint32_t& r2, uint32_t& r3, uint32_t a) {
    asm volatile("ldmatrix.sync.aligned.m8n8.x4.trans.shared.b16 {%0,%1,%2,%3}, [%4];"
                 : "=r"(r0), "=r"(r1), "=r"(r2), "=r"(r3) : "r"(a));
}

__device__ __forceinline__ void mma_bf16(float* d, const uint32_t* a,
                                         const uint32_t* b) {
    asm volatile(
        "mma.sync.aligned.m16n8k16.row.col.f32.bf16.bf16.f32 "
        "{%0,%1,%2,%3}, {%4,%5,%6,%7}, {%8,%9}, {%0,%1,%2,%3};"
        : "+f"(d[0]), "+f"(d[1]), "+f"(d[2]), "+f"(d[3])
        : "r"(a[0]), "r"(a[1]), "r"(a[2]), "r"(a[3]), "r"(b[0]), "r"(b[1]));
}

// split a float pair into packed bf16x2 hi and lo words
__device__ __forceinline__ void split2(float x, float y,
                                       uint32_t& hi, uint32_t& lo) {
    __nv_bfloat16 hx = __float2bfloat16(x), hy = __float2bfloat16(y);
    __nv_bfloat16 lx = __float2bfloat16(x - __bfloat162float(hx));
    __nv_bfloat16 ly = __float2bfloat16(y - __bfloat162float(hy));
    __nv_bfloat162 h2{hx, hy}, l2{lx, ly};
    hi = *reinterpret_cast<uint32_t*>(&h2);
    lo = *reinterpret_cast<uint32_t*>(&l2);
}

// ---------------------------------------------------------------------------
// fp32 -> (hi, lo) bf16 split (for x). n4 = elems/4.
// ---------------------------------------------------------------------------
__global__ __launch_bounds__(256) void split_kernel(
    const float* __restrict__ in, __nv_bfloat16* __restrict__ hi,
    __nv_bfloat16* __restrict__ lo, int n4)
{
    int i = blockIdx.x * blockDim.x + threadIdx.x;
    if (i >= n4) return;
    float4 v = ((const float4*)in)[i];
    uint32_t h0, l0, h1, l1;
    split2(v.x, v.y, h0, l0);
    split2(v.z, v.w, h1, l1);
    uint32_t* H = (uint32_t*)hi;
    uint32_t* L = (uint32_t*)lo;
    H[2 * i] = h0; H[2 * i + 1] = h1;
    L[2 * i] = l0; L[2 * i + 1] = l1;
}

// ---------------------------------------------------------------------------
// W [K,N] fp32 -> WT [N,K] hi/lo bf16 (tiled transpose + split)
// ---------------------------------------------------------------------------
__global__ __launch_bounds__(256) void wsplit_kernel(
    const float* __restrict__ W, __nv_bfloat16* __restrict__ Thi,
    __nv_bfloat16* __restrict__ Tlo, int K, int N)
{
    __shared__ float t[32][33];
    int n0 = blockIdx.x * 32, k0 = blockIdx.y * 32;
    int tx = threadIdx.x, ty = threadIdx.y;
    #pragma unroll
    for (int r = 0; r < 4; r++)
        t[ty + 8 * r][tx] = W[(size_t)(k0 + ty + 8 * r) * N + n0 + tx];
    __syncthreads();
    #pragma unroll
    for (int r = 0; r < 4; r++) {
        float v = t[tx][ty + 8 * r];
        __nv_bfloat16 h = __float2bfloat16(v);
        __nv_bfloat16 l = __float2bfloat16(v - __bfloat162float(h));
        size_t idx = (size_t)(n0 + ty + 8 * r) * K + k0 + tx;
        Thi[idx] = h;
        Tlo[idx] = l;
    }
}

// ---------------------------------------------------------------------------
// Split-bf16 HMMA GEMM: C = A @ W + bias (then either fp32 out, or
// scaled hi/lo bf16 out for downstream tensor-core consumption).
// ---------------------------------------------------------------------------
#define BM 128
#define BN 128
#define BK 64
#define GK 2048
#define NCH (GK / BK)          // 32
#define OFF_AHI 0
#define OFF_ALO 16384
#define OFF_BHI 32768
#define OFF_BLO 49152
#define STG 65536
#define GEMM_SMEM (2 * STG)

__global__ __launch_bounds__(256) void gemm_hmma_kernel(
    const __nv_bfloat16* __restrict__ Ahi, const __nv_bfloat16* __restrict__ Alo,
    const __nv_bfloat16* __restrict__ Bhi, const __nv_bfloat16* __restrict__ Blo,
    const float* __restrict__ bias, float* __restrict__ Cf,
    __nv_bfloat16* __restrict__ Chi, __nv_bfloat16* __restrict__ Clo,
    float scale, int N)
{
    extern __shared__ char dsm[];
    const uint32_t sb = smem_u32(dsm);

    const int tid  = threadIdx.x;
    const int lane = tid & 31;
    const int w    = tid >> 5;
    const int wm   = w & 1;
    const int wn   = w >> 1;
    const int bm   = blockIdx.y * BM;
    const int bn   = blockIdx.x * BN;

    float acc[4][4][4];
    #pragma unroll
    for (int mt = 0; mt < 4; mt++)
        #pragma unroll
        for (int nt = 0; nt < 4; nt++)
            #pragma unroll
            for (int r = 0; r < 4; r++) acc[mt][nt][r] = 0.0f;

    auto load_chunk = [&](int c, int s) {
        uint32_t st = sb + (uint32_t)s * STG;
        int k0 = c * BK;
        #pragma unroll
        for (int i = 0; i < 4; i++) {
            int u = tid + (i << 8);
            int row = u >> 3, c8 = u & 7;
            uint32_t off = (uint32_t)row * 128 +
                           (((uint32_t)c8 * 16) ^ (((uint32_t)(row & 7)) << 4));
            size_t ga = (size_t)(bm + row) * GK + k0 + c8 * 8;
            size_t gb = (size_t)(bn + row) * GK + k0 + c8 * 8;
            cp16(st + OFF_AHI + off, Ahi + ga);
            cp16(st + OFF_ALO + off, Alo + ga);
            cp16(st + OFF_BHI + off, Bhi + gb);
            cp16(st + OFF_BLO + off, Blo + gb);
        }
        CP_COMMIT();
    };

    load_chunk(0, 0);
    load_chunk(1, 1);

    const uint32_t l15  = lane & 15;
    const uint32_t kx   = ((uint32_t)(lane & 7)) << 4;
    const uint32_t hi16 = ((uint32_t)(lane >> 4)) << 4;
    const uint32_t aRow = (uint32_t)(wm * 64 + l15) * 128;
    const uint32_t bRow = (uint32_t)(wn * 32 + l15) * 128;

    for (int c = 0; c < NCH; c++) {
        if (c >= NCH - 1) CP_WAIT0(); else CP_WAIT1();
        __syncthreads();
        uint32_t st = sb + (uint32_t)(c & 1) * STG;

        #pragma unroll
        for (int ks = 0; ks < 4; ks++) {
            uint32_t kp = ((uint32_t)(ks * 32) + hi16) ^ kx;

            uint32_t ah[16], bh[8], bl[8], al[16];
            #pragma unroll
            for (int mt = 0; mt < 4; mt++)
                ldsm4(ah[mt * 4], ah[mt * 4 + 1], ah[mt * 4 + 2], ah[mt * 4 + 3],
                      st + OFF_AHI + aRow + mt * 2048 + kp);
            #pragma unroll
            for (int g = 0; g < 2; g++) {
                uint32_t r0, r1, r2, r3;
                ldsm4(r0, r1, r2, r3, st + OFF_BHI + bRow + g * 2048 + kp);
                bh[g * 4 + 0] = r0; bh[g * 4 + 1] = r2;
                bh[g * 4 + 2] = r1; bh[g * 4 + 3] = r3;
            }
            #pragma unroll
            for (int mt = 0; mt < 4; mt++)
                #pragma unroll
                for (int nt = 0; nt < 4; nt++)
                    mma_bf16(acc[mt][nt], &ah[mt * 4], &bh[nt * 2]);

            #pragma unroll
            for (int g = 0; g < 2; g++) {
                uint32_t r0, r1, r2, r3;
                ldsm4(r0, r1, r2, r3, st + OFF_BLO + bRow + g * 2048 + kp);
                bl[g * 4 + 0] = r0; bl[g * 4 + 1] = r2;
                bl[g * 4 + 2] = r1; bl[g * 4 + 3] = r3;
            }
            #pragma unroll
            for (int mt = 0; mt < 4; mt++)
                #pragma unroll
                for (int nt = 0; nt < 4; nt++)
                    mma_bf16(acc[mt][nt], &ah[mt * 4], &bl[nt * 2]);

            #pragma unroll
            for (int mt = 0; mt < 4; mt++)
                ldsm4(al[mt * 4], al[mt * 4 + 1], al[mt * 4 + 2], al[mt * 4 + 3],
                      st + OFF_ALO + aRow + mt * 2048 + kp);
            #pragma unroll
            for (int mt = 0; mt < 4; mt++)
                #pragma unroll
                for (int nt = 0; nt < 4; nt++)
                    mma_bf16(acc[mt][nt], &al[mt * 4], &bh[nt * 2]);
        }

        __syncthreads();
        if (c + 2 < NCH) load_chunk(c + 2, c & 1);
    }

    // Epilogue
    float bs[4][2];
    #pragma unroll
    for (int nt = 0; nt < 4; nt++) {
        int col = bn + wn * 32 + nt * 8 + (lane & 3) * 2;
        bs[nt][0] = bias[col];
        bs[nt][1] = bias[col + 1];
    }
    #pragma unroll
    for (int mt = 0; mt < 4; mt++) {
        #pragma unroll
        for (int rg = 0; rg < 2; rg++) {
            int row = bm + wm * 64 + mt * 16 + rg * 8 + (lane >> 2);
            #pragma unroll
            for (int nt = 0; nt < 4; nt++) {
                int col = bn + wn * 32 + nt * 8 + (lane & 3) * 2;
                float vx = acc[mt][nt][rg * 2 + 0] + bs[nt][0];
                float vy = acc[mt][nt][rg * 2 + 1] + bs[nt][1];
                if (Cf) {
                    float2 v{vx, vy};
                    *(float2*)(Cf + (size_t)row * N + col) = v;
                } else {
                    uint32_t hi, lo;
                    split2(vx * scale, vy * scale, hi, lo);
                    *(uint32_t*)(Chi + (size_t)row * N + col) = hi;
                    *(uint32_t*)(Clo + (size_t)row * N + col) = lo;
                }
            }
        }
    }
}

// ---------------------------------------------------------------------------
// HMMA flash attention, split-bf16 x3 for both QK^T and PV.
// CTA = (128 q, 1 head, 1 batch); 8 warps x 16 q rows; key tile 64.
// Smem: Qhi/Qlo [128][64] + 2-stage {Khi,Klo,Vhi,Vlo}[64][64]. All rows 128B,
// XOR swizzle (kbyte ^ ((row&7)<<4)).
// Q is pre-scaled by 1/8 in its projection epilogue.
// ---------------------------------------------------------------------------
#define AT_QHI 0
#define AT_QLO 16384
#define AT_ST  32768
#define AT_STG 32768
#define AT_KHI 0
#define AT_KLO 8192
#define AT_VHI 16384
#define AT_VLO 24576
#define AT_SMEM 98304

__global__ __launch_bounds__(256, 2) void attn_hmma_kernel()
{
    extern __shared__ char smraw[];
    const uint32_t sb = smem_u32(smraw);
    const int tid  = threadIdx.x;
    const int lane = tid & 31;
    const int w    = tid >> 5;
    const int qt = blockIdx.x, h = blockIdx.y, b = blockIdx.z;
    const int kvh = h >> 2;
    const int t0  = b * SEQ + qt * 128;

    // Q tile (hi & lo): 128 rows x 64 d
    #pragma unroll
    for (int i = 0; i < 4; i++) {
        int u = tid + (i << 8);
        int row = u >> 3, c8 = u & 7;
        uint32_t off = (uint32_t)row * 128 +
                       (((uint32_t)c8 * 16) ^ (((uint32_t)(row & 7)) << 4));
        size_t g = (size_t)(t0 + row) * HID + h * 64 + c8 * 8;
        cp16(sb + AT_QHI + off, g_Qhi + g);
        cp16(sb + AT_QLO + off, g_Qlo + g);
    }
    CP_COMMIT();

    auto load_kv = [&](int kt, int s) {
        uint32_t st = sb + AT_ST + (uint32_t)s * AT_STG;
        #pragma unroll
        for (int i = 0; i < 2; i++) {
            int u = tid + (i << 8);
            int row = u >> 3, c8 = u & 7;
            uint32_t off = (uint32_t)row * 128 +
                           (((uint32_t)c8 * 16) ^ (((uint32_t)(row & 7)) << 4));
            size_t g = (size_t)(b * SEQ + kt * 64 + row) * KVD + kvh * 64 + c8 * 8;
            cp16(st + AT_KHI + off, g_Khi + g);
            cp16(st + AT_KLO + off, g_Klo + g);
            cp16(st + AT_VHI + off, g_Vhi + g);
            cp16(st + AT_VLO + off, g_Vlo + g);
        }
        CP_COMMIT();
    };
    load_kv(0, 0);
    load_kv(1, 1);

    CP_WAIT1();              // Q + kv0 complete (kv1 in flight)
    __syncthreads();

    const uint32_t kx   = ((uint32_t)(lane & 7)) << 4;
    const uint32_t hi16 = ((uint32_t)(lane >> 4)) << 4;
    const uint32_t l15  = lane & 15;
    const uint32_t qrow = (uint32_t)(w * 16 + l15) * 128;

    // Preload Q-hi fragments for all 4 k-steps (Q-lo reloaded per use)
    uint32_t ah[16];
    #pragma unroll
    for (int ks = 0; ks < 4; ks++) {
        uint32_t kp = ((uint32_t)(ks * 32) + hi16) ^ kx;
        ldsm4(ah[ks * 4], ah[ks * 4 + 1], ah[ks * 4 + 2], ah[ks * 4 + 3],
              sb + AT_QHI + qrow + kp);
    }

    float m0 = -1e30f, m1 = -1e30f, l0 = 0.0f, l1 = 0.0f;
    float o[8][4];
    #pragma unroll
    for (int nt = 0; nt < 8; nt++)
        #pragma unroll
        for (int j = 0; j < 4; j++) o[nt][j] = 0.0f;

    for (int c = 0; c < 32; c++) {
        if (c > 0) {
            if (c == 31) CP_WAIT0(); else CP_WAIT1();
            __syncthreads();
        }
        uint32_t st = sb + AT_ST + (uint32_t)(c & 1) * AT_STG;

        // ---- S = Q K^T (hi*hi + lo*hi + hi*lo) ----
        float s[8][4];
        #pragma unroll
        for (int nt = 0; nt < 8; nt++)
            #pragma unroll
            for (int j = 0; j < 4; j++) s[nt][j] = 0.0f;

        #pragma unroll
        for (int ks = 0; ks < 4; ks++) {
            uint32_t kp = ((uint32_t)(ks * 32) + hi16) ^ kx;
            uint32_t bq[16];
            #pragma unroll
            for (int kg = 0; kg < 4; kg++) {
                uint32_t r0, r1, r2, r3;
                ldsm4(r0, r1, r2, r3,
                      st + AT_KHI + (uint32_t)(kg * 16 + l15) * 128 + kp);
                bq[(2 * kg) * 2]     = r0; bq[(2 * kg) * 2 + 1]     = r2;
                bq[(2 * kg + 1) * 2] = r1; bq[(2 * kg + 1) * 2 + 1] = r3;
            }
            #pragma unroll
            for (int nt = 0; nt < 8; nt++)
                mma_bf16(s[nt], &ah[ks * 4], &bq[nt * 2]);
            {   // Q-lo * K-hi
                uint32_t alx[4];
                ldsm4(alx[0], alx[1], alx[2], alx[3], sb + AT_QLO + qrow + kp);
                #pragma unroll
                for (int nt = 0; nt < 8; nt++)
                    mma_bf16(s[nt], alx, &bq[nt * 2]);
            }
            #pragma unroll
            for (int kg = 0; kg < 4; kg++) {   // K-lo
                uint32_t r0, r1, r2, r3;
                ldsm4(r0, r1, r2, r3,
                      st + AT_KLO + (uint32_t)(kg * 16 + l15) * 128 + kp);
                bq[(2 * kg) * 2]     = r0; bq[(2 * kg) * 2 + 1]     = r2;
                bq[(2 * kg + 1) * 2] = r1; bq[(2 * kg + 1) * 2 + 1] = r3;
            }
            #pragma unroll
            for (int nt = 0; nt < 8; nt++)
                mma_bf16(s[nt], &ah[ks * 4], &bq[nt * 2]);
        }

        // ---- online softmax (rows r=lane>>2 and r+8) ----
        float mx0 = -1e30f, mx1 = -1e30f;
        #pragma unroll
        for (int nt = 0; nt < 8; nt++) {
            mx0 = fmaxf(mx0, fmaxf(s[nt][0], s[nt][1]));
            mx1 = fmaxf(mx1, fmaxf(s[nt][2], s[nt][3]));
        }
        mx0 = fmaxf(mx0, __shfl_xor_sync(0xffffffffu, mx0, 1));
        mx0 = fmaxf(mx0, __shfl_xor_sync(0xffffffffu, mx0, 2));
        mx1 = fmaxf(mx1, __shfl_xor_sync(0xffffffffu, mx1, 1));
        mx1 = fmaxf(mx1, __shfl_xor_sync(0xffffffffu, mx1, 2));
        float m0n = fmaxf(m0, mx0), m1n = fmaxf(m1, mx1);
        float f0 = __expf(m0 - m0n), f1 = __expf(m1 - m1n);
        m0 = m0n; m1 = m1n;
        float ps0 = 0.0f, ps1 = 0.0f;
        #pragma unroll
        for (int nt = 0; nt < 8; nt++) {
            s[nt][0] = __expf(s[nt][0] - m0n); ps0 += s[nt][0];
            s[nt][1] = __expf(s[nt][1] - m0n); ps0 += s[nt][1];
            s[nt][2] = __expf(s[nt][2] - m1n); ps1 += s[nt][2];
            s[nt][3] = __expf(s[nt][3] - m1n); ps1 += s[nt][3];
        }
        ps0 += __shfl_xor_sync(0xffffffffu, ps0, 1);
        ps0 += __shfl_xor_sync(0xffffffffu, ps0, 2);
        ps1 += __shfl_xor_sync(0xffffffffu, ps1, 1);
        ps1 += __shfl_xor_sync(0xffffffffu, ps1, 2);
        l0 = l0 * f0 + ps0;
        l1 = l1 * f1 + ps1;
        #pragma unroll
        for (int nt = 0; nt < 8; nt++) {
            o[nt][0] *= f0; o[nt][1] *= f0;
            o[nt][2] *= f1; o[nt][3] *= f1;
        }

        // ---- O += P V (Ph*Vh + Pl*Vh + Ph*Vl) ----
        const uint32_t vkey = ((uint32_t)((lane >> 3) & 1)) * 8 + (lane & 7);
        const uint32_t vcb  = ((uint32_t)(lane >> 4)) << 4;
        #pragma unroll
        for (int kt = 0; kt < 4; kt++) {
            uint32_t ph[4], pl[4];
            split2(s[2 * kt][0],     s[2 * kt][1],     ph[0], pl[0]);
            split2(s[2 * kt][2],     s[2 * kt][3],     ph[1], pl[1]);
            split2(s[2 * kt + 1][0], s[2 * kt + 1][1], ph[2], pl[2]);
            split2(s[2 * kt + 1][2], s[2 * kt + 1][3], ph[3], pl[3]);

            uint32_t key = (uint32_t)(kt * 16) + vkey;
            uint32_t krow = key * 128;
            uint32_t ksw  = (key & 7) << 4;

            uint32_t vv[16];
            #pragma unroll
            for (int db = 0; db < 4; db++) {   // V-hi
                uint32_t r0, r1, r2, r3;
                ldsm4t(r0, r1, r2, r3,
                       st + AT_VHI + krow + (((uint32_t)db * 32 + vcb) ^ ksw));
                vv[(db * 2) * 2]         = r0; vv[(db * 2) * 2 + 1]     = r1;
                vv[(db * 2 + 1) * 2]     = r2; vv[(db * 2 + 1) * 2 + 1] = r3;
            }
            #pragma unroll
            for (int nt = 0; nt < 8; nt++) mma_bf16(o[nt], ph, &vv[nt * 2]);
            #pragma unroll
            for (int nt = 0; nt < 8; nt++) mma_bf16(o[nt], pl, &vv[nt * 2]);
            #pragma unroll
            for (int db = 0; db < 4; db++) {   // V-lo
                uint32_t r0, r1, r2, r3;
                ldsm4t(r0, r1, r2, r3,
                       st + AT_VLO + krow + (((uint32_t)db * 32 + vcb) ^ ksw));
                vv[(db * 2) * 2]         = r0; vv[(db * 2) * 2 + 1]     = r1;
                vv[(db * 2 + 1) * 2]     = r2; vv[(db * 2 + 1) * 2 + 1] = r3;
            }
            #pragma unroll
            for (int nt = 0; nt < 8; nt++) mma_bf16(o[nt], ph, &vv[nt * 2]);
        }

        __syncthreads();
        if (c + 2 < 32) load_kv(c + 2, c & 1);
    }

    // ---- epilogue: normalize, split to hi/lo bf16 for the O-projection ----
    float il0 = 1.0f / l0, il1 = 1.0f / l1;
    int r = lane >> 2, cb2 = (lane & 3) * 2;
    size_t row0 = (size_t)(t0 + w * 16 + r) * HID + h * 64;
    size_t row1 = row0 + (size_t)8 * HID;
    #pragma unroll
    for (int nt = 0; nt < 8; nt++) {
        int d = nt * 8 + cb2;
        uint32_t hi, lo;
        split2(o[nt][0] * il0, o[nt][1] * il0, hi, lo);
        *(uint32_t*)(g_Chi + row0 + d) = hi;
        *(uint32_t*)(g_Clo + row0 + d) = lo;
        split2(o[nt][2] * il1, o[nt][3] * il1, hi, lo);
        *(uint32_t*)(g_Chi + row1 + d) = hi;
        *(uint32_t*)(g_Clo + row1 + d) = lo;
    }
}

// ---------------------------------------------------------------------------
extern "C" void kernel_launch(void* const* d_in, const int* in_sizes, int n_in,
                              void* d_out, int out_size)
{
    const float* x  = (const float*)d_in[0];
    const float* Wq = (const float*)d_in[1];
    const float* bq = (const float*)d_in[2];
    const float* Wk = (const float*)d_in[3];
    const float* bk = (const float*)d_in[4];
    const float* Wv = (const float*)d_in[5];
    const float* bv = (const float*)d_in[6];
    const float* Wo = (const float*)d_in[7];
    const float* bo = (const float*)d_in[8];
    float* out = (float*)d_out;

    __nv_bfloat16 *xhi, *xlo, *qhi, *qlo, *khi, *klo, *vhi, *vlo, *chi, *clo;
    __nv_bfloat16 *wqh, *wql, *wkh, *wkl, *wvh, *wvl, *woh, *wol;
    cudaGetSymbolAddress((void**)&xhi, g_Xhi);
    cudaGetSymbolAddress((void**)&xlo, g_Xlo);
    cudaGetSymbolAddress((void**)&qhi, g_Qhi);
    cudaGetSymbolAddress((void**)&qlo, g_Qlo);
    cudaGetSymbolAddress((void**)&khi, g_Khi);
    cudaGetSymbolAddress((void**)&klo, g_Klo);
    cudaGetSymbolAddress((void**)&vhi, g_Vhi);
    cudaGetSymbolAddress((void**)&vlo, g_Vlo);
    cudaGetSymbolAddress((void**)&chi, g_Chi);
    cudaGetSymbolAddress((void**)&clo, g_Clo);
    cudaGetSymbolAddress((void**)&wqh, g_WqThi);
    cudaGetSymbolAddress((void**)&wql, g_WqTlo);
    cudaGetSymbolAddress((void**)&wkh, g_WkThi);
    cudaGetSymbolAddress((void**)&wkl, g_WkTlo);
    cudaGetSymbolAddress((void**)&wvh, g_WvThi);
    cudaGetSymbolAddress((void**)&wvl, g_WvTlo);
    cudaGetSymbolAddress((void**)&woh, g_WoThi);
    cudaGetSymbolAddress((void**)&wol, g_WoTlo);

    cudaFuncSetAttribute(gemm_hmma_kernel,
                         cudaFuncAttributeMaxDynamicSharedMemorySize, GEMM_SMEM);
    cudaFuncSetAttribute(attn_hmma_kernel,
                         cudaFuncAttributeMaxDynamicSharedMemorySize, AT_SMEM);

    dim3 blk(256);
    dim3 tblk(32, 8);

    // Operand conversion
    int n4x = TOK * HID / 4;
    split_kernel<<<(n4x + 255) / 256, blk>>>(x, xhi, xlo, n4x);
    wsplit_kernel<<<dim3(HID / 32, HID / 32), tblk>>>(Wq, wqh, wql, HID, HID);
    wsplit_kernel<<<dim3(KVD / 32, HID / 32), tblk>>>(Wk, wkh, wkl, HID, KVD);
    wsplit_kernel<<<dim3(KVD / 32, HID / 32), tblk>>>(Wv, wvh, wvl, HID, KVD);
    wsplit_kernel<<<dim3(HID / 32, HID / 32), tblk>>>(Wo, woh, wol, HID, HID);

    // Projections -> hi/lo bf16 (Q pre-scaled by 1/sqrt(64))
    gemm_hmma_kernel<<<dim3(HID / BN, TOK / BM), blk, GEMM_SMEM>>>(
        xhi, xlo, wqh, wql, bq, nullptr, qhi, qlo, 0.125f, HID);
    gemm_hmma_kernel<<<dim3(KVD / BN, TOK / BM), blk, GEMM_SMEM>>>(
        xhi, xlo, wkh, wkl, bk, nullptr, khi, klo, 1.0f, KVD);
    gemm_hmma_kernel<<<dim3(KVD / BN, TOK / BM), blk, GEMM_SMEM>>>(
        xhi, xlo, wvh, wvl, bv, nullptr, vhi, vlo, 1.0f, KVD);

    // Tensor-core flash attention -> Chi/Clo
    attn_hmma_kernel<<<dim3(16, 32, 2), blk, AT_SMEM>>>();

    // Output projection -> fp32 out
    gemm_hmma_kernel<<<dim3(HID / BN, TOK / BM), blk, GEMM_SMEM>>>(
        chi, clo, woh, wol, bo, out, nullptr, nullptr, 1.0f, HID);
}

// round 15
// speedup vs baseline: 2.6898x; 1.0130x over previous
#include <cuda_runtime.h>
#include <cuda_bf16.h>
#include <cstdint>
#include <cstddef>

#define HID 2048
#define KVD 512
#define TOK 4096   // B*S
#define SEQ 2048

// ---------------------------------------------------------------------------
// Scratch (allocation-guard-safe device globals)
// ---------------------------------------------------------------------------
__device__ __nv_bfloat16 g_Xhi[(size_t)TOK * HID];
__device__ __nv_bfloat16 g_Xlo[(size_t)TOK * HID];
__device__ __nv_bfloat16 g_Qhi[(size_t)TOK * HID];
__device__ __nv_bfloat16 g_Qlo[(size_t)TOK * HID];
__device__ __nv_bfloat16 g_Khi[(size_t)TOK * KVD];
__device__ __nv_bfloat16 g_Klo[(size_t)TOK * KVD];
__device__ __nv_bfloat16 g_Vhi[(size_t)TOK * KVD];
__device__ __nv_bfloat16 g_Vlo[(size_t)TOK * KVD];
__device__ __nv_bfloat16 g_Chi[(size_t)TOK * HID];
__device__ __nv_bfloat16 g_Clo[(size_t)TOK * HID];
__device__ __nv_bfloat16 g_WqThi[(size_t)HID * HID];
__device__ __nv_bfloat16 g_WqTlo[(size_t)HID * HID];
__device__ __nv_bfloat16 g_WkThi[(size_t)KVD * HID];
__device__ __nv_bfloat16 g_WkTlo[(size_t)KVD * HID];
__device__ __nv_bfloat16 g_WvThi[(size_t)KVD * HID];
__device__ __nv_bfloat16 g_WvTlo[(size_t)KVD * HID];
__device__ __nv_bfloat16 g_WoThi[(size_t)HID * HID];
__device__ __nv_bfloat16 g_WoTlo[(size_t)HID * HID];

// ---------------------------------------------------------------------------
// Baseline-ISA helpers (harness targets sm_103 plain: no tcgen05/TMA)
// ---------------------------------------------------------------------------
__device__ __forceinline__ uint32_t smem_u32(const void* p) {
    uint32_t a;
    asm("{ .reg .u64 t; cvta.to.shared.u64 t, %1; cvt.u32.u64 %0, t; }"
        : "=r"(a) : "l"(p));
    return a;
}

__device__ __forceinline__ void cp16(uint32_t s, const void* g) {
    asm volatile("cp.async.cg.shared.global [%0], [%1], 16;" :: "r"(s), "l"(g));
}
#define CP_COMMIT() asm volatile("cp.async.commit_group;" ::: "memory")
#define CP_WAIT1()  asm volatile("cp.async.wait_group 1;" ::: "memory")
#define CP_WAIT0()  asm volatile("cp.async.wait_group 0;" ::: "memory")

__device__ __forceinline__ void ldsm4(uint32_t& r0, uint32_t& r1,
                                      uint32_t& r2, uint32_t& r3, uint32_t a) {
    asm volatile("ldmatrix.sync.aligned.m8n8.x4.shared.b16 {%0,%1,%2,%3}, [%4];"
                 : "=r"(r0), "=r"(r1), "=r"(r2), "=r"(r3) : "r"(a));
}
__device__ __forceinline__ void ldsm4t(uint32_t& r0, uint32_t& r1,
                                       uint32_t& r2, uint32_t& r3, uint32_t a) {
    asm volatile("ldmatrix.sync.aligned.m8n8.x4.trans.shared.b16 {%0,%1,%2,%3}, [%4];"
                 : "=r"(r0), "=r"(r1), "=r"(r2), "=r"(r3) : "r"(a));
}

__device__ __forceinline__ void mma_bf16(float* d, const uint32_t* a,
                                         const uint32_t* b) {
    asm volatile(
        "mma.sync.aligned.m16n8k16.row.col.f32.bf16.bf16.f32 "
        "{%0,%1,%2,%3}, {%4,%5,%6,%7}, {%8,%9}, {%0,%1,%2,%3};"
        : "+f"(d[0]), "+f"(d[1]), "+f"(d[2]), "+f"(d[3])
        : "r"(a[0]), "r"(a[1]), "r"(a[2]), "r"(a[3]), "r"(b[0]), "r"(b[1]));
}

// split a float pair into packed bf16x2 hi and lo words
__device__ __forceinline__ void split2(float x, float y,
                                       uint32_t& hi, uint32_t& lo) {
    __nv_bfloat16 hx = __float2bfloat16(x), hy = __float2bfloat16(y);
    __nv_bfloat16 lx = __float2bfloat16(x - __bfloat162float(hx));
    __nv_bfloat16 ly = __float2bfloat16(y - __bfloat162float(hy));
    __nv_bfloat162 h2{hx, hy}, l2{lx, ly};
    hi = *reinterpret_cast<uint32_t*>(&h2);
    lo = *reinterpret_cast<uint32_t*>(&l2);
}

// ---------------------------------------------------------------------------
// fp32 -> (hi, lo) bf16 split (for x). n4 = elems/4.
// ---------------------------------------------------------------------------
__global__ __launch_bounds__(256) void split_kernel(
    const float* __restrict__ in, __nv_bfloat16* __restrict__ hi,
    __nv_bfloat16* __restrict__ lo, int n4)
{
    int i = blockIdx.x * blockDim.x + threadIdx.x;
    if (i >= n4) return;
    float4 v = ((const float4*)in)[i];
    uint32_t h0, l0, h1, l1;
    split2(v.x, v.y, h0, l0);
    split2(v.z, v.w, h1, l1);
    uint32_t* H = (uint32_t*)hi;
    uint32_t* L = (uint32_t*)lo;
    H[2 * i] = h0; H[2 * i + 1] = h1;
    L[2 * i] = l0; L[2 * i + 1] = l1;
}

// ---------------------------------------------------------------------------
// ALL weight transposes+splits in one launch. z routes {Wq, Wk, Wv, Wo}.
// W [2048, Nout] fp32 -> WT [Nout, 2048] hi/lo bf16.
// ---------------------------------------------------------------------------
__global__ __launch_bounds__(256) void wsplit_all_kernel(
    const float* __restrict__ Wq, const float* __restrict__ Wk,
    const float* __restrict__ Wv, const float* __restrict__ Wo)
{
    const int z = blockIdx.z;
    const float* W;
    __nv_bfloat16 *Th, *Tl;
    int Nout;
    if (z == 0)      { W = Wq; Th = g_WqThi; Tl = g_WqTlo; Nout = HID; }
    else if (z == 1) { W = Wk; Th = g_WkThi; Tl = g_WkTlo; Nout = KVD; }
    else if (z == 2) { W = Wv; Th = g_WvThi; Tl = g_WvTlo; Nout = KVD; }
    else             { W = Wo; Th = g_WoThi; Tl = g_WoTlo; Nout = HID; }

    int n0 = blockIdx.x * 32, k0 = blockIdx.y * 32;
    if (n0 >= Nout) return;

    __shared__ float t[32][33];
    int tx = threadIdx.x, ty = threadIdx.y;
    #pragma unroll
    for (int r = 0; r < 4; r++)
        t[ty + 8 * r][tx] = W[(size_t)(k0 + ty + 8 * r) * Nout + n0 + tx];
    __syncthreads();
    #pragma unroll
    for (int r = 0; r < 4; r++) {
        float v = t[tx][ty + 8 * r];
        __nv_bfloat16 h = __float2bfloat16(v);
        __nv_bfloat16 l = __float2bfloat16(v - __bfloat162float(h));
        size_t idx = (size_t)(n0 + ty + 8 * r) * HID + k0 + tx;
        Th[idx] = h;
        Tl[idx] = l;
    }
}

// ---------------------------------------------------------------------------
// GEMM tile constants (shared by fused QKV kernel and O kernel)
// ---------------------------------------------------------------------------
#define BM 128
#define BN 128
#define BK 64
#define GK 2048
#define NCH (GK / BK)          // 32
#define OFF_AHI 0
#define OFF_ALO 16384
#define OFF_BHI 32768
#define OFF_BLO 49152
#define STG 65536
#define GEMM_SMEM (2 * STG)

// Shared mainloop body: accumulates split-bf16 x3 into acc[4][4][4].
// Ahi/Alo are [M,2048] K-major; Bh/Bl are [N,2048] K-major (row bnW-based).
__device__ __forceinline__ void gemm_mainloop(
    const __nv_bfloat16* __restrict__ Ahi, const __nv_bfloat16* __restrict__ Alo,
    const __nv_bfloat16* __restrict__ Bh,  const __nv_bfloat16* __restrict__ Bl,
    int bm, int bnW, uint32_t sb, int tid, int lane, int wm, int wn,
    float acc[4][4][4])
{
    auto load_chunk = [&](int c, int s) {
        uint32_t st = sb + (uint32_t)s * STG;
        int k0 = c * BK;
        #pragma unroll
        for (int i = 0; i < 4; i++) {
            int u = tid + (i << 8);
            int row = u >> 3, c8 = u & 7;
            uint32_t off = (uint32_t)row * 128 +
                           (((uint32_t)c8 * 16) ^ (((uint32_t)(row & 7)) << 4));
            size_t ga = (size_t)(bm + row) * GK + k0 + c8 * 8;
            size_t gb = (size_t)(bnW + row) * GK + k0 + c8 * 8;
            cp16(st + OFF_AHI + off, Ahi + ga);
            cp16(st + OFF_ALO + off, Alo + ga);
            cp16(st + OFF_BHI + off, Bh + gb);
            cp16(st + OFF_BLO + off, Bl + gb);
        }
        CP_COMMIT();
    };

    load_chunk(0, 0);
    load_chunk(1, 1);

    const uint32_t l15  = lane & 15;
    const uint32_t kx   = ((uint32_t)(lane & 7)) << 4;
    const uint32_t hi16 = ((uint32_t)(lane >> 4)) << 4;
    const uint32_t aRow = (uint32_t)(wm * 64 + l15) * 128;
    const uint32_t bRow = (uint32_t)(wn * 32 + l15) * 128;

    for (int c = 0; c < NCH; c++) {
        if (c >= NCH - 1) CP_WAIT0(); else CP_WAIT1();
        __syncthreads();
        uint32_t st = sb + (uint32_t)(c & 1) * STG;

        #pragma unroll
        for (int ks = 0; ks < 4; ks++) {
            uint32_t kp = ((uint32_t)(ks * 32) + hi16) ^ kx;

            uint32_t ah[16], bh[8], bl[8], al[16];
            #pragma unroll
            for (int mt = 0; mt < 4; mt++)
                ldsm4(ah[mt * 4], ah[mt * 4 + 1], ah[mt * 4 + 2], ah[mt * 4 + 3],
                      st + OFF_AHI + aRow + mt * 2048 + kp);
            #pragma unroll
            for (int g = 0; g < 2; g++) {
                uint32_t r0, r1, r2, r3;
                ldsm4(r0, r1, r2, r3, st + OFF_BHI + bRow + g * 2048 + kp);
                bh[g * 4 + 0] = r0; bh[g * 4 + 1] = r2;
                bh[g * 4 + 2] = r1; bh[g * 4 + 3] = r3;
            }
            #pragma unroll
            for (int mt = 0; mt < 4; mt++)
                #pragma unroll
                for (int nt = 0; nt < 4; nt++)
                    mma_bf16(acc[mt][nt], &ah[mt * 4], &bh[nt * 2]);

            #pragma unroll
            for (int g = 0; g < 2; g++) {
                uint32_t r0, r1, r2, r3;
                ldsm4(r0, r1, r2, r3, st + OFF_BLO + bRow + g * 2048 + kp);
                bl[g * 4 + 0] = r0; bl[g * 4 + 1] = r2;
                bl[g * 4 + 2] = r1; bl[g * 4 + 3] = r3;
            }
            #pragma unroll
            for (int mt = 0; mt < 4; mt++)
                #pragma unroll
                for (int nt = 0; nt < 4; nt++)
                    mma_bf16(acc[mt][nt], &ah[mt * 4], &bl[nt * 2]);

            #pragma unroll
            for (int mt = 0; mt < 4; mt++)
                ldsm4(al[mt * 4], al[mt * 4 + 1], al[mt * 4 + 2], al[mt * 4 + 3],
                      st + OFF_ALO + aRow + mt * 2048 + kp);
            #pragma unroll
            for (int mt = 0; mt < 4; mt++)
                #pragma unroll
                for (int nt = 0; nt < 4; nt++)
                    mma_bf16(acc[mt][nt], &al[mt * 4], &bh[nt * 2]);
        }

        __syncthreads();
        if (c + 2 < NCH) load_chunk(c + 2, c & 1);
    }
}

// ---------------------------------------------------------------------------
// Fused Q/K/V projection: X @ {Wq,Wk,Wv} + bias -> hi/lo bf16.
// grid.x routing: [0,16) Q tiles, [16,20) K tiles, [20,24) V tiles.
// ---------------------------------------------------------------------------
__global__ __launch_bounds__(256) void qkv_hmma_kernel(
    const float* __restrict__ bq, const float* __restrict__ bk,
    const float* __restrict__ bv)
{
    extern __shared__ char dsm[];
    const uint32_t sb = smem_u32(dsm);

    const int tid  = threadIdx.x;
    const int lane = tid & 31;
    const int w    = tid >> 5;
    const int wm   = w & 1;
    const int wn   = w >> 1;
    const int bm   = blockIdx.y * BM;
    const int bx   = blockIdx.x;

    const __nv_bfloat16 *Bh, *Bl;
    __nv_bfloat16 *Ch, *Cl;
    const float* bias;
    float scale;
    int Nw, bn;
    if (bx < 16) {
        Bh = g_WqThi; Bl = g_WqTlo; Ch = g_Qhi; Cl = g_Qlo;
        bias = bq; scale = 0.125f; Nw = HID; bn = bx * 128;
    } else if (bx < 20) {
        Bh = g_WkThi; Bl = g_WkTlo; Ch = g_Khi; Cl = g_Klo;
        bias = bk; scale = 1.0f; Nw = KVD; bn = (bx - 16) * 128;
    } else {
        Bh = g_WvThi; Bl = g_WvTlo; Ch = g_Vhi; Cl = g_Vlo;
        bias = bv; scale = 1.0f; Nw = KVD; bn = (bx - 20) * 128;
    }

    float acc[4][4][4];
    #pragma unroll
    for (int mt = 0; mt < 4; mt++)
        #pragma unroll
        for (int nt = 0; nt < 4; nt++)
            #pragma unroll
            for (int r = 0; r < 4; r++) acc[mt][nt][r] = 0.0f;

    gemm_mainloop(g_Xhi, g_Xlo, Bh, Bl, bm, bn, sb, tid, lane, wm, wn, acc);

    // Epilogue: bias, scale, split to hi/lo bf16
    float bs[4][2];
    #pragma unroll
    for (int nt = 0; nt < 4; nt++) {
        int col = bn + wn * 32 + nt * 8 + (lane & 3) * 2;
        bs[nt][0] = bias[col];
        bs[nt][1] = bias[col + 1];
    }
    #pragma unroll
    for (int mt = 0; mt < 4; mt++) {
        #pragma unroll
        for (int rg = 0; rg < 2; rg++) {
            int row = bm + wm * 64 + mt * 16 + rg * 8 + (lane >> 2);
            #pragma unroll
            for (int nt = 0; nt < 4; nt++) {
                int col = bn + wn * 32 + nt * 8 + (lane & 3) * 2;
                float vx = (acc[mt][nt][rg * 2 + 0] + bs[nt][0]) * scale;
                float vy = (acc[mt][nt][rg * 2 + 1] + bs[nt][1]) * scale;
                uint32_t hi, lo;
                split2(vx, vy, hi, lo);
                *(uint32_t*)(Ch + (size_t)row * Nw + col) = hi;
                *(uint32_t*)(Cl + (size_t)row * Nw + col) = lo;
            }
        }
    }
}

// ---------------------------------------------------------------------------
// O projection: Chi/Clo @ Wo + bo -> fp32 out
// ---------------------------------------------------------------------------
__global__ __launch_bounds__(256) void oproj_hmma_kernel(
    const float* __restrict__ bo, float* __restrict__ out)
{
    extern __shared__ char dsm[];
    const uint32_t sb = smem_u32(dsm);

    const int tid  = threadIdx.x;
    const int lane = tid & 31;
    const int w    = tid >> 5;
    const int wm   = w & 1;
    const int wn   = w >> 1;
    const int bm   = blockIdx.y * BM;
    const int bn   = blockIdx.x * BN;

    float acc[4][4][4];
    #pragma unroll
    for (int mt = 0; mt < 4; mt++)
        #pragma unroll
        for (int nt = 0; nt < 4; nt++)
            #pragma unroll
            for (int r = 0; r < 4; r++) acc[mt][nt][r] = 0.0f;

    gemm_mainloop(g_Chi, g_Clo, g_WoThi, g_WoTlo, bm, bn, sb, tid, lane, wm, wn, acc);

    float bs[4][2];
    #pragma unroll
    for (int nt = 0; nt < 4; nt++) {
        int col = bn + wn * 32 + nt * 8 + (lane & 3) * 2;
        bs[nt][0] = bo[col];
        bs[nt][1] = bo[col + 1];
    }
    #pragma unroll
    for (int mt = 0; mt < 4; mt++) {
        #pragma unroll
        for (int rg = 0; rg < 2; rg++) {
            int row = bm + wm * 64 + mt * 16 + rg * 8 + (lane >> 2);
            #pragma unroll
            for (int nt = 0; nt < 4; nt++) {
                int col = bn + wn * 32 + nt * 8 + (lane & 3) * 2;
                float2 v;
                v.x = acc[mt][nt][rg * 2 + 0] + bs[nt][0];
                v.y = acc[mt][nt][rg * 2 + 1] + bs[nt][1];
                *(float2*)(out + (size_t)row * HID + col) = v;
            }
        }
    }
}

// ---------------------------------------------------------------------------
// HMMA flash attention, split-bf16 x3 for both QK^T and PV. (verified R13)
// ---------------------------------------------------------------------------
#define AT_QHI 0
#define AT_QLO 16384
#define AT_ST  32768
#define AT_STG 32768
#define AT_KHI 0
#define AT_KLO 8192
#define AT_VHI 16384
#define AT_VLO 24576
#define AT_SMEM 98304

__global__ __launch_bounds__(256, 2) void attn_hmma_kernel()
{
    extern __shared__ char smraw[];
    const uint32_t sb = smem_u32(smraw);
    const int tid  = threadIdx.x;
    const int lane = tid & 31;
    const int w    = tid >> 5;
    const int qt = blockIdx.x, h = blockIdx.y, b = blockIdx.z;
    const int kvh = h >> 2;
    const int t0  = b * SEQ + qt * 128;

    // Q tile (hi & lo): 128 rows x 64 d
    #pragma unroll
    for (int i = 0; i < 4; i++) {
        int u = tid + (i << 8);
        int row = u >> 3, c8 = u & 7;
        uint32_t off = (uint32_t)row * 128 +
                       (((uint32_t)c8 * 16) ^ (((uint32_t)(row & 7)) << 4));
        size_t g = (size_t)(t0 + row) * HID + h * 64 + c8 * 8;
        cp16(sb + AT_QHI + off, g_Qhi + g);
        cp16(sb + AT_QLO + off, g_Qlo + g);
    }
    CP_COMMIT();

    auto load_kv = [&](int kt, int s) {
        uint32_t st = sb + AT_ST + (uint32_t)s * AT_STG;
        #pragma unroll
        for (int i = 0; i < 2; i++) {
            int u = tid + (i << 8);
            int row = u >> 3, c8 = u & 7;
            uint32_t off = (uint32_t)row * 128 +
                           (((uint32_t)c8 * 16) ^ (((uint32_t)(row & 7)) << 4));
            size_t g = (size_t)(b * SEQ + kt * 64 + row) * KVD + kvh * 64 + c8 * 8;
            cp16(st + AT_KHI + off, g_Khi + g);
            cp16(st + AT_KLO + off, g_Klo + g);
            cp16(st + AT_VHI + off, g_Vhi + g);
            cp16(st + AT_VLO + off, g_Vlo + g);
        }
        CP_COMMIT();
    };
    load_kv(0, 0);
    load_kv(1, 1);

    CP_WAIT1();
    __syncthreads();

    const uint32_t kx   = ((uint32_t)(lane & 7)) << 4;
    const uint32_t hi16 = ((uint32_t)(lane >> 4)) << 4;
    const uint32_t l15  = lane & 15;
    const uint32_t qrow = (uint32_t)(w * 16 + l15) * 128;

    uint32_t ah[16];
    #pragma unroll
    for (int ks = 0; ks < 4; ks++) {
        uint32_t kp = ((uint32_t)(ks * 32) + hi16) ^ kx;
        ldsm4(ah[ks * 4], ah[ks * 4 + 1], ah[ks * 4 + 2], ah[ks * 4 + 3],
              sb + AT_QHI + qrow + kp);
    }

    float m0 = -1e30f, m1 = -1e30f, l0 = 0.0f, l1 = 0.0f;
    float o[8][4];
    #pragma unroll
    for (int nt = 0; nt < 8; nt++)
        #pragma unroll
        for (int j = 0; j < 4; j++) o[nt][j] = 0.0f;

    for (int c = 0; c < 32; c++) {
        if (c > 0) {
            if (c == 31) CP_WAIT0(); else CP_WAIT1();
            __syncthreads();
        }
        uint32_t st = sb + AT_ST + (uint32_t)(c & 1) * AT_STG;

        float s[8][4];
        #pragma unroll
        for (int nt = 0; nt < 8; nt++)
            #pragma unroll
            for (int j = 0; j < 4; j++) s[nt][j] = 0.0f;

        #pragma unroll
        for (int ks = 0; ks < 4; ks++) {
            uint32_t kp = ((uint32_t)(ks * 32) + hi16) ^ kx;
            uint32_t bq[16];
            #pragma unroll
            for (int kg = 0; kg < 4; kg++) {
                uint32_t r0, r1, r2, r3;
                ldsm4(r0, r1, r2, r3,
                      st + AT_KHI + (uint32_t)(kg * 16 + l15) * 128 + kp);
                bq[(2 * kg) * 2]     = r0; bq[(2 * kg) * 2 + 1]     = r2;
                bq[(2 * kg + 1) * 2] = r1; bq[(2 * kg + 1) * 2 + 1] = r3;
            }
            #pragma unroll
            for (int nt = 0; nt < 8; nt++)
                mma_bf16(s[nt], &ah[ks * 4], &bq[nt * 2]);
            {
                uint32_t alx[4];
                ldsm4(alx[0], alx[1], alx[2], alx[3], sb + AT_QLO + qrow + kp);
                #pragma unroll
                for (int nt = 0; nt < 8; nt++)
                    mma_bf16(s[nt], alx, &bq[nt * 2]);
            }
            #pragma unroll
            for (int kg = 0; kg < 4; kg++) {
                uint32_t r0, r1, r2, r3;
                ldsm4(r0, r1, r2, r3,
                      st + AT_KLO + (uint32_t)(kg * 16 + l15) * 128 + kp);
                bq[(2 * kg) * 2]     = r0; bq[(2 * kg) * 2 + 1]     = r2;
                bq[(2 * kg + 1) * 2] = r1; bq[(2 * kg + 1) * 2 + 1] = r3;
            }
            #pragma unroll
            for (int nt = 0; nt < 8; nt++)
                mma_bf16(s[nt], &ah[ks * 4], &bq[nt * 2]);
        }

        float mx0 = -1e30f, mx1 = -1e30f;
        #pragma unroll
        for (int nt = 0; nt < 8; nt++) {
            mx0 = fmaxf(mx0, fmaxf(s[nt][0], s[nt][1]));
            mx1 = fmaxf(mx1, fmaxf(s[nt][2], s[nt][3]));
        }
        mx0 = fmaxf(mx0, __shfl_xor_sync(0xffffffffu, mx0, 1));
        mx0 = fmaxf(mx0, __shfl_xor_sync(0xffffffffu, mx0, 2));
        mx1 = fmaxf(mx1, __shfl_xor_sync(0xffffffffu, mx1, 1));
        mx1 = fmaxf(mx1, __shfl_xor_sync(0xffffffffu, mx1, 2));
        float m0n = fmaxf(m0, mx0), m1n = fmaxf(m1, mx1);
        float f0 = __expf(m0 - m0n), f1 = __expf(m1 - m1n);
        m0 = m0n; m1 = m1n;
        float ps0 = 0.0f, ps1 = 0.0f;
        #pragma unroll
        for (int nt = 0; nt < 8; nt++) {
            s[nt][0] = __expf(s[nt][0] - m0n); ps0 += s[nt][0];
            s[nt][1] = __expf(s[nt][1] - m0n); ps0 += s[nt][1];
            s[nt][2] = __expf(s[nt][2] - m1n); ps1 += s[nt][2];
            s[nt][3] = __expf(s[nt][3] - m1n); ps1 += s[nt][3];
        }
        ps0 += __shfl_xor_sync(0xffffffffu, ps0, 1);
        ps0 += __shfl_xor_sync(0xffffffffu, ps0, 2);
        ps1 += __shfl_xor_sync(0xffffffffu, ps1, 1);
        ps1 += __shfl_xor_sync(0xffffffffu, ps1, 2);
        l0 = l0 * f0 + ps0;
        l1 = l1 * f1 + ps1;
        #pragma unroll
        for (int nt = 0; nt < 8; nt++) {
            o[nt][0] *= f0; o[nt][1] *= f0;
            o[nt][2] *= f1; o[nt][3] *= f1;
        }

        const uint32_t vkey = ((uint32_t)((lane >> 3) & 1)) * 8 + (lane & 7);
        const uint32_t vcb  = ((uint32_t)(lane >> 4)) << 4;
        #pragma unroll
        for (int kt = 0; kt < 4; kt++) {
            uint32_t ph[4], pl[4];
            split2(s[2 * kt][0],     s[2 * kt][1],     ph[0], pl[0]);
            split2(s[2 * kt][2],     s[2 * kt][3],     ph[1], pl[1]);
            split2(s[2 * kt + 1][0], s[2 * kt + 1][1], ph[2], pl[2]);
            split2(s[2 * kt + 1][2], s[2 * kt + 1][3], ph[3], pl[3]);

            uint32_t key = (uint32_t)(kt * 16) + vkey;
            uint32_t krow = key * 128;
            uint32_t ksw  = (key & 7) << 4;

            uint32_t vv[16];
            #pragma unroll
            for (int db = 0; db < 4; db++) {
                uint32_t r0, r1, r2, r3;
                ldsm4t(r0, r1, r2, r3,
                       st + AT_VHI + krow + (((uint32_t)db * 32 + vcb) ^ ksw));
                vv[(db * 2) * 2]         = r0; vv[(db * 2) * 2 + 1]     = r1;
                vv[(db * 2 + 1) * 2]     = r2; vv[(db * 2 + 1) * 2 + 1] = r3;
            }
            #pragma unroll
            for (int nt = 0; nt < 8; nt++) mma_bf16(o[nt], ph, &vv[nt * 2]);
            #pragma unroll
            for (int nt = 0; nt < 8; nt++) mma_bf16(o[nt], pl, &vv[nt * 2]);
            #pragma unroll
            for (int db = 0; db < 4; db++) {
                uint32_t r0, r1, r2, r3;
                ldsm4t(r0, r1, r2, r3,
                       st + AT_VLO + krow + (((uint32_t)db * 32 + vcb) ^ ksw));
                vv[(db * 2) * 2]         = r0; vv[(db * 2) * 2 + 1]     = r1;
                vv[(db * 2 + 1) * 2]     = r2; vv[(db * 2 + 1) * 2 + 1] = r3;
            }
            #pragma unroll
            for (int nt = 0; nt < 8; nt++) mma_bf16(o[nt], ph, &vv[nt * 2]);
        }

        __syncthreads();
        if (c + 2 < 32) load_kv(c + 2, c & 1);
    }

    float il0 = 1.0f / l0, il1 = 1.0f / l1;
    int r = lane >> 2, cb2 = (lane & 3) * 2;
    size_t row0 = (size_t)(t0 + w * 16 + r) * HID + h * 64;
    size_t row1 = row0 + (size_t)8 * HID;
    #pragma unroll
    for (int nt = 0; nt < 8; nt++) {
        int d = nt * 8 + cb2;
        uint32_t hi, lo;
        split2(o[nt][0] * il0, o[nt][1] * il0, hi, lo);
        *(uint32_t*)(g_Chi + row0 + d) = hi;
        *(uint32_t*)(g_Clo + row0 + d) = lo;
        split2(o[nt][2] * il1, o[nt][3] * il1, hi, lo);
        *(uint32_t*)(g_Chi + row1 + d) = hi;
        *(uint32_t*)(g_Clo + row1 + d) = lo;
    }
}

// ---------------------------------------------------------------------------
extern "C" void kernel_launch(void* const* d_in, const int* in_sizes, int n_in,
                              void* d_out, int out_size)
{
    const float* x  = (const float*)d_in[0];
    const float* Wq = (const float*)d_in[1];
    const float* bq = (const float*)d_in[2];
    const float* Wk = (const float*)d_in[3];
    const float* bk = (const float*)d_in[4];
    const float* Wv = (const float*)d_in[5];
    const float* bv = (const float*)d_in[6];
    const float* Wo = (const float*)d_in[7];
    const float* bo = (const float*)d_in[8];
    float* out = (float*)d_out;

    __nv_bfloat16 *xhi, *xlo;
    cudaGetSymbolAddress((void**)&xhi, g_Xhi);
    cudaGetSymbolAddress((void**)&xlo, g_Xlo);

    cudaFuncSetAttribute(qkv_hmma_kernel,
                         cudaFuncAttributeMaxDynamicSharedMemorySize, GEMM_SMEM);
    cudaFuncSetAttribute(oproj_hmma_kernel,
                         cudaFuncAttributeMaxDynamicSharedMemorySize, GEMM_SMEM);
    cudaFuncSetAttribute(attn_hmma_kernel,
                         cudaFuncAttributeMaxDynamicSharedMemorySize, AT_SMEM);

    dim3 blk(256);

    // Operand conversion (2 launches)
    int n4x = TOK * HID / 4;
    split_kernel<<<(n4x + 255) / 256, blk>>>(x, xhi, xlo, n4x);
    wsplit_all_kernel<<<dim3(64, 64, 4), dim3(32, 8)>>>(Wq, Wk, Wv, Wo);

    // Fused QKV projections (768 CTAs, one launch)
    qkv_hmma_kernel<<<dim3(24, TOK / BM), blk, GEMM_SMEM>>>(bq, bk, bv);

    // Tensor-core flash attention -> Chi/Clo
    attn_hmma_kernel<<<dim3(16, 32, 2), blk, AT_SMEM>>>();

    // Output projection -> fp32 out
    oproj_hmma_kernel<<<dim3(HID / BN, TOK / BM), blk, GEMM_SMEM>>>(bo, out);
}